// round 13
// baseline (speedup 1.0000x reference)
#include <cuda_runtime.h>
#include <cuda_fp16.h>

#define N_NODES 100000
#define N_EDGES 1600000
#define N_GRAPH 64
#define H 128
// Wf1 input dim = H + SV + AD = 128 + 64 + 32
#define ZDIM 224

#define SCAN_T 1024
#define SCAN_B ((N_NODES + SCAN_T - 1) / SCAN_T)   // 98

// ---------------- scratch (device globals: allocation-free) ----------------
__device__ float  g_dis[N_NODES];
__device__ int    g_hist[N_NODES];               // in-degree (dst histogram)
__device__ int    g_off [N_NODES];               // CSR row offsets (exclusive scan)
__device__ int    g_cur [N_NODES];               // fill cursors
__device__ int    g_bsum[SCAN_B];
__device__ int    g_csrc[N_EDGES];               // CSR: src ids grouped by dst
__device__ __half g_h [(size_t)N_NODES * H];     // h' = dis * (A @ W) (gather source)
__device__ __half g_a [(size_t)N_NODES * H];     // relu(dis*agg1 + b1) = GEMM-2 input
__device__ float  g_pool[N_GRAPH * H];
__device__ float  g_cnt[N_GRAPH];

// ---------------- setup: histogram, rsqrt, scan, CSR fill ----------------
__global__ void k_init() {
    int i = blockIdx.x * blockDim.x + threadIdx.x;
    if (i < N_NODES) { g_hist[i] = 0; g_cur[i] = 0; }
    if (i < N_GRAPH * H) g_pool[i] = 0.0f;
    if (i < N_GRAPH) g_cnt[i] = 0.0f;
}

__global__ void k_hist(const int* __restrict__ ei) {
    int i = blockIdx.x * blockDim.x + threadIdx.x;
    if (i < N_EDGES) {
        int d = ei[N_EDGES + i];
        if ((unsigned)d < N_NODES) atomicAdd(&g_hist[d], 1);
    }
}

__global__ void k_rsqrt() {
    int i = blockIdx.x * blockDim.x + threadIdx.x;
    if (i < N_NODES) g_dis[i] = rsqrtf((float)g_hist[i] + 1.0f);   // +1 self loop
}

__global__ __launch_bounds__(SCAN_T) void k_scan_block() {
    __shared__ int sh[SCAN_T];
    int i = blockIdx.x * SCAN_T + threadIdx.x;
    int v = (i < N_NODES) ? g_hist[i] : 0;
    sh[threadIdx.x] = v;
    __syncthreads();
#pragma unroll
    for (int o = 1; o < SCAN_T; o <<= 1) {
        int t = (threadIdx.x >= o) ? sh[threadIdx.x - o] : 0;
        __syncthreads();
        sh[threadIdx.x] += t;
        __syncthreads();
    }
    if (i < N_NODES) g_off[i] = sh[threadIdx.x] - v;               // exclusive
    if (threadIdx.x == SCAN_T - 1) g_bsum[blockIdx.x] = sh[SCAN_T - 1];
}

__global__ void k_scan_top() {
    if (threadIdx.x == 0) {
        int acc = 0;
#pragma unroll 1
        for (int i = 0; i < SCAN_B; i++) { int t = g_bsum[i]; g_bsum[i] = acc; acc += t; }
    }
}

__global__ __launch_bounds__(SCAN_T) void k_scan_add() {
    int i = blockIdx.x * SCAN_T + threadIdx.x;
    if (i < N_NODES) g_off[i] += g_bsum[blockIdx.x];
}

__global__ void k_fill(const int* __restrict__ ei) {
    int i = blockIdx.x * blockDim.x + threadIdx.x;
    if (i < N_EDGES) {
        int s = ei[i];
        int d = ei[N_EDGES + i];
        if ((unsigned)s >= N_NODES || (unsigned)d >= N_NODES) return;
        int pos = g_off[d] + atomicAdd(&g_cur[d], 1);
        g_csrc[pos] = s;
    }
}

// ---------------- tf32 tensor-core GEMM: g_h = dis[row]*(A @ W), fp16 write ------
#define BM 128
#define ASTR 132
#define WSTR 136
#define GEMM_SMEM ((BM * ASTR + 128 * WSTR + 128) * 4)

__device__ __forceinline__ float f2tf32(float f) {
    unsigned u;
    asm("cvt.rna.tf32.f32 %0, %1;" : "=r"(u) : "f"(f));
    return __uint_as_float(u);
}

__device__ __forceinline__ void mma_tf32(float& d0, float& d1, float& d2, float& d3,
                                         unsigned a0, unsigned a1, unsigned a2, unsigned a3,
                                         unsigned b0, unsigned b1) {
    asm volatile("mma.sync.aligned.m16n8k8.row.col.f32.tf32.tf32.f32 "
                 "{%0,%1,%2,%3}, {%4,%5,%6,%7}, {%8,%9}, {%0,%1,%2,%3};"
                 : "+f"(d0), "+f"(d1), "+f"(d2), "+f"(d3)
                 : "r"(a0), "r"(a1), "r"(a2), "r"(a3), "r"(b0), "r"(b1));
}

// LAYER==0: A = x (fp32 ext).  LAYER==1: A = g_a (fp16, already relu'd).
template<int LAYER>
__global__ __launch_bounds__(256) void k_gemm(const float* __restrict__ x,
                                              const float* __restrict__ W) {
    extern __shared__ float smem[];
    float* As   = smem;                          // [BM][ASTR]
    float* Ws   = smem + BM * ASTR;              // [128][WSTR]
    float* sdis = smem + BM * ASTR + 128 * WSTR; // [128]

    int tid = threadIdx.x;
    int row0 = blockIdx.x * BM;

    if (tid < 128) {
        int gr = row0 + tid;
        sdis[tid] = (gr < N_NODES) ? g_dis[gr] : 0.f;
    }

    const float4* W4 = (const float4*)W;
#pragma unroll
    for (int i = 0; i < 16; i++) {
        int j = tid + i * 256;
        int r = j >> 5, c4 = j & 31;
        float4 v = W4[j];
        *(float4*)&Ws[r * WSTR + c4 * 4] =
            make_float4(f2tf32(v.x), f2tf32(v.y), f2tf32(v.z), f2tf32(v.w));
    }

    if (LAYER == 0) {
#pragma unroll
        for (int i = 0; i < 16; i++) {
            int j = tid + i * 256;
            int r = j >> 5, c4 = j & 31;
            int gr = row0 + r;
            float4 v = make_float4(0.f, 0.f, 0.f, 0.f);
            if (gr < N_NODES) v = *(const float4*)&x[(size_t)gr * H + c4 * 4];
            *(float4*)&As[r * ASTR + c4 * 4] =
                make_float4(f2tf32(v.x), f2tf32(v.y), f2tf32(v.z), f2tf32(v.w));
        }
    } else {
#pragma unroll
        for (int i = 0; i < 8; i++) {
            int j = tid + i * 256;
            int r = j >> 4, c8 = j & 15;
            int gr = row0 + r;
            float o[8];
            if (gr < N_NODES) {
                uint4 u = *(const uint4*)&g_a[(size_t)gr * H + c8 * 8];
                float2 f0 = __half22float2(*(__half2*)&u.x);
                float2 f1 = __half22float2(*(__half2*)&u.y);
                float2 f2 = __half22float2(*(__half2*)&u.z);
                float2 f3 = __half22float2(*(__half2*)&u.w);
                o[0] = f2tf32(f0.x); o[1] = f2tf32(f0.y);
                o[2] = f2tf32(f1.x); o[3] = f2tf32(f1.y);
                o[4] = f2tf32(f2.x); o[5] = f2tf32(f2.y);
                o[6] = f2tf32(f3.x); o[7] = f2tf32(f3.y);
            } else {
#pragma unroll
                for (int t = 0; t < 8; t++) o[t] = 0.f;
            }
            *(float4*)&As[r * ASTR + c8 * 8]     = make_float4(o[0], o[1], o[2], o[3]);
            *(float4*)&As[r * ASTR + c8 * 8 + 4] = make_float4(o[4], o[5], o[6], o[7]);
        }
    }
    __syncthreads();

    int lane = tid & 31, wid = tid >> 5;
    int wm = wid >> 1, wn = wid & 1;
    int g8 = lane >> 2, tig = lane & 3;

    float acc[2][8][4];
#pragma unroll
    for (int mf = 0; mf < 2; mf++)
#pragma unroll
        for (int nf = 0; nf < 8; nf++)
#pragma unroll
            for (int q = 0; q < 4; q++) acc[mf][nf][q] = 0.f;

#pragma unroll 1
    for (int kk = 0; kk < 16; kk++) {
        int k0 = kk * 8;
        unsigned b[8][2];
#pragma unroll
        for (int nf = 0; nf < 8; nf++) {
            int n = wn * 64 + nf * 8 + g8;
            b[nf][0] = __float_as_uint(Ws[(k0 + tig) * WSTR + n]);
            b[nf][1] = __float_as_uint(Ws[(k0 + tig + 4) * WSTR + n]);
        }
#pragma unroll
        for (int mf = 0; mf < 2; mf++) {
            int r = wm * 32 + mf * 16 + g8;
            unsigned a0 = __float_as_uint(As[r * ASTR + k0 + tig]);
            unsigned a1 = __float_as_uint(As[(r + 8) * ASTR + k0 + tig]);
            unsigned a2 = __float_as_uint(As[r * ASTR + k0 + tig + 4]);
            unsigned a3 = __float_as_uint(As[(r + 8) * ASTR + k0 + tig + 4]);
#pragma unroll
            for (int nf = 0; nf < 8; nf++)
                mma_tf32(acc[mf][nf][0], acc[mf][nf][1], acc[mf][nf][2], acc[mf][nf][3],
                         a0, a1, a2, a3, b[nf][0], b[nf][1]);
        }
    }

#pragma unroll
    for (int mf = 0; mf < 2; mf++) {
#pragma unroll
        for (int hh = 0; hh < 2; hh++) {
            int lr = wm * 32 + mf * 16 + g8 + hh * 8;
            int gr = row0 + lr;
            if (gr >= N_NODES) continue;
            float dsc = sdis[lr];
#pragma unroll
            for (int nf = 0; nf < 8; nf++) {
                float v0 = acc[mf][nf][hh * 2 + 0] * dsc;
                float v1 = acc[mf][nf][hh * 2 + 1] * dsc;
                size_t off = (size_t)gr * H + wn * 64 + nf * 8 + 2 * tig;
                *(__half2*)&g_h[off] = __floats2half2_rn(v0, v1);
            }
        }
    }
}

// ---------------- CSR aggregate: warp/node, prefetched indices, 4-deep pipeline --
// agg = g_h[v] + sum_{src in csr[v]} g_h[src];  r = relu(dis[v]*agg + bias)
// PHASE 0: r -> g_a (fp16, GEMM-2 input).
// PHASE 1: block-staged mean-pool: smem accumulate, 128 global atomics per block.
#define AGG_NPB 8   // nodes per block (8 warps)

__device__ __forceinline__ void acc_row(int s, int lane,
                                        float& a0, float& a1, float& a2, float& a3) {
    uint2 u = *(const uint2*)&g_h[(size_t)s * H + lane * 4];
    float2 p0 = __half22float2(*(__half2*)&u.x);
    float2 p1 = __half22float2(*(__half2*)&u.y);
    a0 += p0.x; a1 += p0.y; a2 += p1.x; a3 += p1.y;
}

template<int PHASE>
__global__ __launch_bounds__(256) void k_agg(const float* __restrict__ bias,
                                             const int* __restrict__ batch) {
    __shared__ float sp[H];
    __shared__ int s_uni;

    int warp = threadIdx.x >> 5;
    int lane = threadIdx.x & 31;
    int v = blockIdx.x * AGG_NPB + warp;

    if (PHASE == 1) {
        if (threadIdx.x < H) sp[threadIdx.x] = 0.f;
        if (threadIdx.x == 0) {
            int v0 = blockIdx.x * AGG_NPB;
            int vl = min(v0 + AGG_NPB - 1, N_NODES - 1);
            int b0 = batch[v0];
            s_uni = (b0 == batch[vl]) ? b0 : -1;
        }
        __syncthreads();
    }

    if (v < N_NODES) {
        // self-loop seed
        float a0, a1, a2, a3;
        {
            uint2 u = *(const uint2*)&g_h[(size_t)v * H + lane * 4];
            float2 f0 = __half22float2(*(__half2*)&u.x);
            float2 f1 = __half22float2(*(__half2*)&u.y);
            a0 = f0.x; a1 = f0.y; a2 = f1.x; a3 = f1.y;
        }

        int beg = g_off[v];
        int deg = g_hist[v];
#pragma unroll 1
        for (int base = 0; base < deg; base += 32) {
            int n = min(32, deg - base);
            // one coalesced load fetches up to 32 neighbor indices
            int myidx = (lane < n) ? __ldg(&g_csrc[beg + base + lane]) : 0;
            int j = 0;
#pragma unroll 1
            for (; j + 4 <= n; j += 4) {         // 4 independent 256B row loads in flight
                int s0 = __shfl_sync(0xffffffffu, myidx, j);
                int s1 = __shfl_sync(0xffffffffu, myidx, j + 1);
                int s2 = __shfl_sync(0xffffffffu, myidx, j + 2);
                int s3 = __shfl_sync(0xffffffffu, myidx, j + 3);
                uint2 u0 = *(const uint2*)&g_h[(size_t)s0 * H + lane * 4];
                uint2 u1 = *(const uint2*)&g_h[(size_t)s1 * H + lane * 4];
                uint2 u2 = *(const uint2*)&g_h[(size_t)s2 * H + lane * 4];
                uint2 u3 = *(const uint2*)&g_h[(size_t)s3 * H + lane * 4];
                float2 p0 = __half22float2(*(__half2*)&u0.x), p1 = __half22float2(*(__half2*)&u0.y);
                float2 q0 = __half22float2(*(__half2*)&u1.x), q1 = __half22float2(*(__half2*)&u1.y);
                float2 r0_ = __half22float2(*(__half2*)&u2.x), r1_ = __half22float2(*(__half2*)&u2.y);
                float2 t0 = __half22float2(*(__half2*)&u3.x), t1 = __half22float2(*(__half2*)&u3.y);
                a0 += (p0.x + q0.x) + (r0_.x + t0.x);
                a1 += (p0.y + q0.y) + (r0_.y + t0.y);
                a2 += (p1.x + q1.x) + (r1_.x + t1.x);
                a3 += (p1.y + q1.y) + (r1_.y + t1.y);
            }
#pragma unroll 1
            for (; j < n; j++) {
                int s0 = __shfl_sync(0xffffffffu, myidx, j);
                acc_row(s0, lane, a0, a1, a2, a3);
            }
        }

        float dsc = g_dis[v];
        float4 bb = *(const float4*)&bias[lane * 4];
        float r0 = fmaxf(fmaf(dsc, a0, bb.x), 0.f);
        float r1 = fmaxf(fmaf(dsc, a1, bb.y), 0.f);
        float r2 = fmaxf(fmaf(dsc, a2, bb.z), 0.f);
        float r3 = fmaxf(fmaf(dsc, a3, bb.w), 0.f);

        if (PHASE == 0) {
            uint2 o;
            *(__half2*)&o.x = __floats2half2_rn(r0, r1);
            *(__half2*)&o.y = __floats2half2_rn(r2, r3);
            *(uint2*)&g_a[(size_t)v * H + lane * 4] = o;
        } else {
            if (s_uni >= 0) {                    // whole block same graph: stage in smem
                atomicAdd(&sp[lane * 4 + 0], r0);
                atomicAdd(&sp[lane * 4 + 1], r1);
                atomicAdd(&sp[lane * 4 + 2], r2);
                atomicAdd(&sp[lane * 4 + 3], r3);
            } else {                             // graph boundary block (rare): direct
                int b = __ldg(&batch[v]);
                float* pp = &g_pool[b * H + lane * 4];
                atomicAdd(pp + 0, r0);
                atomicAdd(pp + 1, r1);
                atomicAdd(pp + 2, r2);
                atomicAdd(pp + 3, r3);
                if (lane == 0) atomicAdd(&g_cnt[b], 1.0f);
            }
        }
    }

    if (PHASE == 1) {
        __syncthreads();
        if (s_uni >= 0) {
            if (threadIdx.x < H) atomicAdd(&g_pool[s_uni * H + threadIdx.x], sp[threadIdx.x]);
            if (threadIdx.x == 0) {
                int cnt = min(AGG_NPB, N_NODES - blockIdx.x * AGG_NPB);
                atomicAdd(&g_cnt[s_uni], (float)cnt);
            }
        }
    }
}

// ---------------- head MLP: 64 blocks, one per graph ----------------
__global__ __launch_bounds__(256) void k_mlp(const float* __restrict__ sv,
                                             const float* __restrict__ act,
                                             const float* __restrict__ Wf1, const float* __restrict__ bf1,
                                             const float* __restrict__ Wf2, const float* __restrict__ bf2,
                                             const float* __restrict__ Wo,  const float* __restrict__ bo,
                                             float* __restrict__ out) {
    int g = blockIdx.x;
    int t = threadIdx.x;
    __shared__ float z[ZDIM];
    __shared__ float z1[256];
    __shared__ float z2[256];
    __shared__ float red[8];

    if (t < ZDIM) {
        float v;
        if (t < 128)      v = g_pool[g * H + t] / fmaxf(g_cnt[g], 1.0f);
        else if (t < 192) v = sv[g * 64 + (t - 128)];
        else              v = act[g * 32 + (t - 192)];
        z[t] = v;
    }
    __syncthreads();

    float a = bf1[t];
#pragma unroll 8
    for (int k = 0; k < ZDIM; k++) a = fmaf(z[k], Wf1[k * 256 + t], a);
    z1[t] = fmaxf(a, 0.f);
    __syncthreads();

    a = bf2[t];
#pragma unroll 8
    for (int k = 0; k < 256; k++) a = fmaf(z1[k], Wf2[k * 256 + t], a);
    z2[t] = fmaxf(a, 0.f);
    __syncthreads();

    float p = z2[t] * Wo[t];
#pragma unroll
    for (int o = 16; o > 0; o >>= 1) p += __shfl_down_sync(0xffffffffu, p, o);
    if ((t & 31) == 0) red[t >> 5] = p;
    __syncthreads();
    if (t == 0) {
        float sacc = 0.f;
#pragma unroll
        for (int i = 0; i < 8; i++) sacc += red[i];
        out[g] = sacc + bo[0];
    }
}

// ---------------- launch ----------------
extern "C" void kernel_launch(void* const* d_in, const int* in_sizes, int n_in,
                              void* d_out, int out_size) {
    const float* x     = (const float*)d_in[0];
    const int*   ei    = (const int*)d_in[1];
    const int*   batch = (const int*)d_in[2];
    const float* sv    = (const float*)d_in[3];
    const float* act   = (const float*)d_in[4];
    const float* W1    = (const float*)d_in[5];
    const float* b1    = (const float*)d_in[6];
    const float* W2    = (const float*)d_in[7];
    const float* b2    = (const float*)d_in[8];
    const float* Wf1   = (const float*)d_in[9];
    const float* bf1   = (const float*)d_in[10];
    const float* Wf2   = (const float*)d_in[11];
    const float* bf2   = (const float*)d_in[12];
    const float* Wo    = (const float*)d_in[13];
    const float* bo    = (const float*)d_in[14];
    float* out = (float*)d_out;

    cudaFuncSetAttribute(k_gemm<0>, cudaFuncAttributeMaxDynamicSharedMemorySize, GEMM_SMEM);
    cudaFuncSetAttribute(k_gemm<1>, cudaFuncAttributeMaxDynamicSharedMemorySize, GEMM_SMEM);

    // setup + CSR build (reused by both layers)
    k_init      <<<(N_NODES + 255) / 256, 256>>>();
    k_hist      <<<(N_EDGES + 255) / 256, 256>>>(ei);
    k_rsqrt     <<<(N_NODES + 255) / 256, 256>>>();
    k_scan_block<<<SCAN_B, SCAN_T>>>();
    k_scan_top  <<<1, 32>>>();
    k_scan_add  <<<SCAN_B, SCAN_T>>>();
    k_fill      <<<(N_EDGES + 255) / 256, 256>>>(ei);

    int gemm_blocks = (N_NODES + BM - 1) / BM;              // 782
    int agg_blocks  = (N_NODES + AGG_NPB - 1) / AGG_NPB;    // 12500

    k_gemm<0><<<gemm_blocks, 256, GEMM_SMEM>>>(x, W1);
    k_agg<0> <<<agg_blocks, 256>>>(b1, batch);              // -> g_a
    k_gemm<1><<<gemm_blocks, 256, GEMM_SMEM>>>(x, W2);
    k_agg<1> <<<agg_blocks, 256>>>(b2, batch);              // -> g_pool (block-staged)

    k_mlp<<<N_GRAPH, 256>>>(sv, act, Wf1, bf1, Wf2, bf2, Wo, bo, out);
}

// round 14
// speedup vs baseline: 1.0036x; 1.0036x over previous
#include <cuda_runtime.h>
#include <cuda_fp16.h>

#define N_NODES 100000
#define N_EDGES 1600000
#define N_GRAPH 64
#define H 128
// Wf1 input dim = H + SV + AD = 128 + 64 + 32
#define ZDIM 224

#define SCAN_T 1024
#define SCAN_B ((N_NODES + SCAN_T - 1) / SCAN_T)   // 98

// ---------------- scratch (device globals: allocation-free) ----------------
__device__ float  g_dis[N_NODES];
__device__ int    g_hist[N_NODES];               // in-degree (dst histogram)
__device__ int    g_off [N_NODES];               // CSR row offsets (exclusive scan)
__device__ int    g_cur [N_NODES];               // fill cursors
__device__ int    g_bsum[SCAN_B];
__device__ int    g_csrc[N_EDGES];               // CSR: src ids grouped by dst
__device__ __half g_h [(size_t)N_NODES * H];     // h' = dis * (A @ W) (gather source)
__device__ __half g_a [(size_t)N_NODES * H];     // relu(dis*agg1 + b1) = GEMM-2 input
__device__ float  g_pool[N_GRAPH * H];
__device__ float  g_cnt[N_GRAPH];

// ---------------- setup: histogram, rsqrt, scan, CSR fill ----------------
__global__ void k_init() {
    int i = blockIdx.x * blockDim.x + threadIdx.x;
    if (i < N_NODES) { g_hist[i] = 0; g_cur[i] = 0; }
    if (i < N_GRAPH * H) g_pool[i] = 0.0f;
    if (i < N_GRAPH) g_cnt[i] = 0.0f;
}

__global__ void k_hist(const int* __restrict__ ei) {
    int i = blockIdx.x * blockDim.x + threadIdx.x;
    if (i < N_EDGES) {
        int d = ei[N_EDGES + i];
        if ((unsigned)d < N_NODES) atomicAdd(&g_hist[d], 1);
    }
}

__global__ void k_rsqrt() {
    int i = blockIdx.x * blockDim.x + threadIdx.x;
    if (i < N_NODES) g_dis[i] = rsqrtf((float)g_hist[i] + 1.0f);   // +1 self loop
}

__global__ __launch_bounds__(SCAN_T) void k_scan_block() {
    __shared__ int sh[SCAN_T];
    int i = blockIdx.x * SCAN_T + threadIdx.x;
    int v = (i < N_NODES) ? g_hist[i] : 0;
    sh[threadIdx.x] = v;
    __syncthreads();
#pragma unroll
    for (int o = 1; o < SCAN_T; o <<= 1) {
        int t = (threadIdx.x >= o) ? sh[threadIdx.x - o] : 0;
        __syncthreads();
        sh[threadIdx.x] += t;
        __syncthreads();
    }
    if (i < N_NODES) g_off[i] = sh[threadIdx.x] - v;               // exclusive
    if (threadIdx.x == SCAN_T - 1) g_bsum[blockIdx.x] = sh[SCAN_T - 1];
}

__global__ void k_scan_top() {
    if (threadIdx.x == 0) {
        int acc = 0;
#pragma unroll 1
        for (int i = 0; i < SCAN_B; i++) { int t = g_bsum[i]; g_bsum[i] = acc; acc += t; }
    }
}

__global__ __launch_bounds__(SCAN_T) void k_scan_add() {
    int i = blockIdx.x * SCAN_T + threadIdx.x;
    if (i < N_NODES) g_off[i] += g_bsum[blockIdx.x];
}

__global__ void k_fill(const int* __restrict__ ei) {
    int i = blockIdx.x * blockDim.x + threadIdx.x;
    if (i < N_EDGES) {
        int s = ei[i];
        int d = ei[N_EDGES + i];
        if ((unsigned)s >= N_NODES || (unsigned)d >= N_NODES) return;
        int pos = g_off[d] + atomicAdd(&g_cur[d], 1);
        g_csrc[pos] = s;
    }
}

// ---------------- tf32 tensor-core GEMM: g_h = dis[row]*(A @ W), fp16 write ------
#define BM 128
#define ASTR 132
#define WSTR 136
#define GEMM_SMEM ((BM * ASTR + 128 * WSTR + 128) * 4)

__device__ __forceinline__ float f2tf32(float f) {
    unsigned u;
    asm("cvt.rna.tf32.f32 %0, %1;" : "=r"(u) : "f"(f));
    return __uint_as_float(u);
}

__device__ __forceinline__ void mma_tf32(float& d0, float& d1, float& d2, float& d3,
                                         unsigned a0, unsigned a1, unsigned a2, unsigned a3,
                                         unsigned b0, unsigned b1) {
    asm volatile("mma.sync.aligned.m16n8k8.row.col.f32.tf32.tf32.f32 "
                 "{%0,%1,%2,%3}, {%4,%5,%6,%7}, {%8,%9}, {%0,%1,%2,%3};"
                 : "+f"(d0), "+f"(d1), "+f"(d2), "+f"(d3)
                 : "r"(a0), "r"(a1), "r"(a2), "r"(a3), "r"(b0), "r"(b1));
}

// LAYER==0: A = x (fp32 ext).  LAYER==1: A = g_a (fp16, already relu'd).
template<int LAYER>
__global__ __launch_bounds__(256) void k_gemm(const float* __restrict__ x,
                                              const float* __restrict__ W) {
    extern __shared__ float smem[];
    float* As   = smem;                          // [BM][ASTR]
    float* Ws   = smem + BM * ASTR;              // [128][WSTR]
    float* sdis = smem + BM * ASTR + 128 * WSTR; // [128]

    int tid = threadIdx.x;
    int row0 = blockIdx.x * BM;

    if (tid < 128) {
        int gr = row0 + tid;
        sdis[tid] = (gr < N_NODES) ? g_dis[gr] : 0.f;
    }

    const float4* W4 = (const float4*)W;
#pragma unroll
    for (int i = 0; i < 16; i++) {
        int j = tid + i * 256;
        int r = j >> 5, c4 = j & 31;
        float4 v = W4[j];
        *(float4*)&Ws[r * WSTR + c4 * 4] =
            make_float4(f2tf32(v.x), f2tf32(v.y), f2tf32(v.z), f2tf32(v.w));
    }

    if (LAYER == 0) {
#pragma unroll
        for (int i = 0; i < 16; i++) {
            int j = tid + i * 256;
            int r = j >> 5, c4 = j & 31;
            int gr = row0 + r;
            float4 v = make_float4(0.f, 0.f, 0.f, 0.f);
            if (gr < N_NODES) v = *(const float4*)&x[(size_t)gr * H + c4 * 4];
            *(float4*)&As[r * ASTR + c4 * 4] =
                make_float4(f2tf32(v.x), f2tf32(v.y), f2tf32(v.z), f2tf32(v.w));
        }
    } else {
#pragma unroll
        for (int i = 0; i < 8; i++) {
            int j = tid + i * 256;
            int r = j >> 4, c8 = j & 15;
            int gr = row0 + r;
            float o[8];
            if (gr < N_NODES) {
                uint4 u = *(const uint4*)&g_a[(size_t)gr * H + c8 * 8];
                float2 f0 = __half22float2(*(__half2*)&u.x);
                float2 f1 = __half22float2(*(__half2*)&u.y);
                float2 f2 = __half22float2(*(__half2*)&u.z);
                float2 f3 = __half22float2(*(__half2*)&u.w);
                o[0] = f2tf32(f0.x); o[1] = f2tf32(f0.y);
                o[2] = f2tf32(f1.x); o[3] = f2tf32(f1.y);
                o[4] = f2tf32(f2.x); o[5] = f2tf32(f2.y);
                o[6] = f2tf32(f3.x); o[7] = f2tf32(f3.y);
            } else {
#pragma unroll
                for (int t = 0; t < 8; t++) o[t] = 0.f;
            }
            *(float4*)&As[r * ASTR + c8 * 8]     = make_float4(o[0], o[1], o[2], o[3]);
            *(float4*)&As[r * ASTR + c8 * 8 + 4] = make_float4(o[4], o[5], o[6], o[7]);
        }
    }
    __syncthreads();

    int lane = tid & 31, wid = tid >> 5;
    int wm = wid >> 1, wn = wid & 1;
    int g8 = lane >> 2, tig = lane & 3;

    float acc[2][8][4];
#pragma unroll
    for (int mf = 0; mf < 2; mf++)
#pragma unroll
        for (int nf = 0; nf < 8; nf++)
#pragma unroll
            for (int q = 0; q < 4; q++) acc[mf][nf][q] = 0.f;

#pragma unroll 1
    for (int kk = 0; kk < 16; kk++) {
        int k0 = kk * 8;
        unsigned b[8][2];
#pragma unroll
        for (int nf = 0; nf < 8; nf++) {
            int n = wn * 64 + nf * 8 + g8;
            b[nf][0] = __float_as_uint(Ws[(k0 + tig) * WSTR + n]);
            b[nf][1] = __float_as_uint(Ws[(k0 + tig + 4) * WSTR + n]);
        }
#pragma unroll
        for (int mf = 0; mf < 2; mf++) {
            int r = wm * 32 + mf * 16 + g8;
            unsigned a0 = __float_as_uint(As[r * ASTR + k0 + tig]);
            unsigned a1 = __float_as_uint(As[(r + 8) * ASTR + k0 + tig]);
            unsigned a2 = __float_as_uint(As[r * ASTR + k0 + tig + 4]);
            unsigned a3 = __float_as_uint(As[(r + 8) * ASTR + k0 + tig + 4]);
#pragma unroll
            for (int nf = 0; nf < 8; nf++)
                mma_tf32(acc[mf][nf][0], acc[mf][nf][1], acc[mf][nf][2], acc[mf][nf][3],
                         a0, a1, a2, a3, b[nf][0], b[nf][1]);
        }
    }

#pragma unroll
    for (int mf = 0; mf < 2; mf++) {
#pragma unroll
        for (int hh = 0; hh < 2; hh++) {
            int lr = wm * 32 + mf * 16 + g8 + hh * 8;
            int gr = row0 + lr;
            if (gr >= N_NODES) continue;
            float dsc = sdis[lr];
#pragma unroll
            for (int nf = 0; nf < 8; nf++) {
                float v0 = acc[mf][nf][hh * 2 + 0] * dsc;
                float v1 = acc[mf][nf][hh * 2 + 1] * dsc;
                size_t off = (size_t)gr * H + wn * 64 + nf * 8 + 2 * tig;
                *(__half2*)&g_h[off] = __floats2half2_rn(v0, v1);
            }
        }
    }
}

// ---------------- CSR aggregate: warp/node, prefetched indices, 4-deep pipeline --
// agg = g_h[v] + sum_{src in csr[v]} g_h[src];  r = relu(dis[v]*agg + bias)
// PHASE 0: r -> g_a (fp16, GEMM-2 input).
// PHASE 1: block-staged mean-pool: smem accumulate, 128 global atomics per block.
#define AGG_NPB 8   // nodes per block (8 warps)

__device__ __forceinline__ void acc_row(int s, int lane,
                                        float& a0, float& a1, float& a2, float& a3) {
    uint2 u = *(const uint2*)&g_h[(size_t)s * H + lane * 4];
    float2 p0 = __half22float2(*(__half2*)&u.x);
    float2 p1 = __half22float2(*(__half2*)&u.y);
    a0 += p0.x; a1 += p0.y; a2 += p1.x; a3 += p1.y;
}

template<int PHASE>
__global__ __launch_bounds__(256) void k_agg(const float* __restrict__ bias,
                                             const int* __restrict__ batch) {
    __shared__ float sp[H];
    __shared__ int s_uni;

    int warp = threadIdx.x >> 5;
    int lane = threadIdx.x & 31;
    int v = blockIdx.x * AGG_NPB + warp;

    if (PHASE == 1) {
        if (threadIdx.x < H) sp[threadIdx.x] = 0.f;
        if (threadIdx.x == 0) {
            int v0 = blockIdx.x * AGG_NPB;
            int vl = min(v0 + AGG_NPB - 1, N_NODES - 1);
            int b0 = batch[v0];
            s_uni = (b0 == batch[vl]) ? b0 : -1;
        }
        __syncthreads();
    }

    if (v < N_NODES) {
        // self-loop seed
        float a0, a1, a2, a3;
        {
            uint2 u = *(const uint2*)&g_h[(size_t)v * H + lane * 4];
            float2 f0 = __half22float2(*(__half2*)&u.x);
            float2 f1 = __half22float2(*(__half2*)&u.y);
            a0 = f0.x; a1 = f0.y; a2 = f1.x; a3 = f1.y;
        }

        int beg = g_off[v];
        int deg = g_hist[v];
#pragma unroll 1
        for (int base = 0; base < deg; base += 32) {
            int n = min(32, deg - base);
            // one coalesced load fetches up to 32 neighbor indices
            int myidx = (lane < n) ? __ldg(&g_csrc[beg + base + lane]) : 0;
            int j = 0;
#pragma unroll 1
            for (; j + 4 <= n; j += 4) {         // 4 independent 256B row loads in flight
                int s0 = __shfl_sync(0xffffffffu, myidx, j);
                int s1 = __shfl_sync(0xffffffffu, myidx, j + 1);
                int s2 = __shfl_sync(0xffffffffu, myidx, j + 2);
                int s3 = __shfl_sync(0xffffffffu, myidx, j + 3);
                uint2 u0 = *(const uint2*)&g_h[(size_t)s0 * H + lane * 4];
                uint2 u1 = *(const uint2*)&g_h[(size_t)s1 * H + lane * 4];
                uint2 u2 = *(const uint2*)&g_h[(size_t)s2 * H + lane * 4];
                uint2 u3 = *(const uint2*)&g_h[(size_t)s3 * H + lane * 4];
                float2 p0 = __half22float2(*(__half2*)&u0.x), p1 = __half22float2(*(__half2*)&u0.y);
                float2 q0 = __half22float2(*(__half2*)&u1.x), q1 = __half22float2(*(__half2*)&u1.y);
                float2 r0_ = __half22float2(*(__half2*)&u2.x), r1_ = __half22float2(*(__half2*)&u2.y);
                float2 t0 = __half22float2(*(__half2*)&u3.x), t1 = __half22float2(*(__half2*)&u3.y);
                a0 += (p0.x + q0.x) + (r0_.x + t0.x);
                a1 += (p0.y + q0.y) + (r0_.y + t0.y);
                a2 += (p1.x + q1.x) + (r1_.x + t1.x);
                a3 += (p1.y + q1.y) + (r1_.y + t1.y);
            }
#pragma unroll 1
            for (; j < n; j++) {
                int s0 = __shfl_sync(0xffffffffu, myidx, j);
                acc_row(s0, lane, a0, a1, a2, a3);
            }
        }

        float dsc = g_dis[v];
        float4 bb = *(const float4*)&bias[lane * 4];
        float r0 = fmaxf(fmaf(dsc, a0, bb.x), 0.f);
        float r1 = fmaxf(fmaf(dsc, a1, bb.y), 0.f);
        float r2 = fmaxf(fmaf(dsc, a2, bb.z), 0.f);
        float r3 = fmaxf(fmaf(dsc, a3, bb.w), 0.f);

        if (PHASE == 0) {
            uint2 o;
            *(__half2*)&o.x = __floats2half2_rn(r0, r1);
            *(__half2*)&o.y = __floats2half2_rn(r2, r3);
            *(uint2*)&g_a[(size_t)v * H + lane * 4] = o;
        } else {
            if (s_uni >= 0) {                    // whole block same graph: stage in smem
                atomicAdd(&sp[lane * 4 + 0], r0);
                atomicAdd(&sp[lane * 4 + 1], r1);
                atomicAdd(&sp[lane * 4 + 2], r2);
                atomicAdd(&sp[lane * 4 + 3], r3);
            } else {                             // graph boundary block (rare): direct
                int b = __ldg(&batch[v]);
                float* pp = &g_pool[b * H + lane * 4];
                atomicAdd(pp + 0, r0);
                atomicAdd(pp + 1, r1);
                atomicAdd(pp + 2, r2);
                atomicAdd(pp + 3, r3);
                if (lane == 0) atomicAdd(&g_cnt[b], 1.0f);
            }
        }
    }

    if (PHASE == 1) {
        __syncthreads();
        if (s_uni >= 0) {
            if (threadIdx.x < H) atomicAdd(&g_pool[s_uni * H + threadIdx.x], sp[threadIdx.x]);
            if (threadIdx.x == 0) {
                int cnt = min(AGG_NPB, N_NODES - blockIdx.x * AGG_NPB);
                atomicAdd(&g_cnt[s_uni], (float)cnt);
            }
        }
    }
}

// ---------------- head MLP: 64 blocks, one per graph ----------------
__global__ __launch_bounds__(256) void k_mlp(const float* __restrict__ sv,
                                             const float* __restrict__ act,
                                             const float* __restrict__ Wf1, const float* __restrict__ bf1,
                                             const float* __restrict__ Wf2, const float* __restrict__ bf2,
                                             const float* __restrict__ Wo,  const float* __restrict__ bo,
                                             float* __restrict__ out) {
    int g = blockIdx.x;
    int t = threadIdx.x;
    __shared__ float z[ZDIM];
    __shared__ float z1[256];
    __shared__ float z2[256];
    __shared__ float red[8];

    if (t < ZDIM) {
        float v;
        if (t < 128)      v = g_pool[g * H + t] / fmaxf(g_cnt[g], 1.0f);
        else if (t < 192) v = sv[g * 64 + (t - 128)];
        else              v = act[g * 32 + (t - 192)];
        z[t] = v;
    }
    __syncthreads();

    float a = bf1[t];
#pragma unroll 8
    for (int k = 0; k < ZDIM; k++) a = fmaf(z[k], Wf1[k * 256 + t], a);
    z1[t] = fmaxf(a, 0.f);
    __syncthreads();

    a = bf2[t];
#pragma unroll 8
    for (int k = 0; k < 256; k++) a = fmaf(z1[k], Wf2[k * 256 + t], a);
    z2[t] = fmaxf(a, 0.f);
    __syncthreads();

    float p = z2[t] * Wo[t];
#pragma unroll
    for (int o = 16; o > 0; o >>= 1) p += __shfl_down_sync(0xffffffffu, p, o);
    if ((t & 31) == 0) red[t >> 5] = p;
    __syncthreads();
    if (t == 0) {
        float sacc = 0.f;
#pragma unroll
        for (int i = 0; i < 8; i++) sacc += red[i];
        out[g] = sacc + bo[0];
    }
}

// ---------------- launch ----------------
extern "C" void kernel_launch(void* const* d_in, const int* in_sizes, int n_in,
                              void* d_out, int out_size) {
    const float* x     = (const float*)d_in[0];
    const int*   ei    = (const int*)d_in[1];
    const int*   batch = (const int*)d_in[2];
    const float* sv    = (const float*)d_in[3];
    const float* act   = (const float*)d_in[4];
    const float* W1    = (const float*)d_in[5];
    const float* b1    = (const float*)d_in[6];
    const float* W2    = (const float*)d_in[7];
    const float* b2    = (const float*)d_in[8];
    const float* Wf1   = (const float*)d_in[9];
    const float* bf1   = (const float*)d_in[10];
    const float* Wf2   = (const float*)d_in[11];
    const float* bf2   = (const float*)d_in[12];
    const float* Wo    = (const float*)d_in[13];
    const float* bo    = (const float*)d_in[14];
    float* out = (float*)d_out;

    cudaFuncSetAttribute(k_gemm<0>, cudaFuncAttributeMaxDynamicSharedMemorySize, GEMM_SMEM);
    cudaFuncSetAttribute(k_gemm<1>, cudaFuncAttributeMaxDynamicSharedMemorySize, GEMM_SMEM);

    // setup + CSR build (reused by both layers)
    k_init      <<<(N_NODES + 255) / 256, 256>>>();
    k_hist      <<<(N_EDGES + 255) / 256, 256>>>(ei);
    k_rsqrt     <<<(N_NODES + 255) / 256, 256>>>();
    k_scan_block<<<SCAN_B, SCAN_T>>>();
    k_scan_top  <<<1, 32>>>();
    k_scan_add  <<<SCAN_B, SCAN_T>>>();
    k_fill      <<<(N_EDGES + 255) / 256, 256>>>(ei);

    int gemm_blocks = (N_NODES + BM - 1) / BM;              // 782
    int agg_blocks  = (N_NODES + AGG_NPB - 1) / AGG_NPB;    // 12500

    k_gemm<0><<<gemm_blocks, 256, GEMM_SMEM>>>(x, W1);
    k_agg<0> <<<agg_blocks, 256>>>(b1, batch);              // -> g_a
    k_gemm<1><<<gemm_blocks, 256, GEMM_SMEM>>>(x, W2);
    k_agg<1> <<<agg_blocks, 256>>>(b2, batch);              // -> g_pool (block-staged)

    k_mlp<<<N_GRAPH, 256>>>(sv, act, Wf1, bf1, Wf2, bf2, Wo, bo, out);
}

// round 15
// speedup vs baseline: 1.0343x; 1.0306x over previous
#include <cuda_runtime.h>
#include <cuda_fp16.h>

#define N_NODES 100000
#define N_EDGES 1600000
#define N_GRAPH 64
#define H 128
// Wf1 input dim = H + SV + AD = 128 + 64 + 32
#define ZDIM 224

#define SCAN_T 1024
#define SCAN_B ((N_NODES + SCAN_T - 1) / SCAN_T)   // 98

// ---------------- scratch (device globals: allocation-free) ----------------
__device__ float  g_dis[N_NODES];
__device__ int    g_hist[N_NODES];               // in-degree (dst histogram)
__device__ int    g_off [N_NODES];               // CSR row offsets (exclusive scan)
__device__ int    g_cur [N_NODES];               // fill cursors
__device__ int    g_bsum[SCAN_B];
__device__ int    g_csrc[N_EDGES];               // CSR: src ids grouped by dst
__device__ __half g_h [(size_t)N_NODES * H];     // h' = dis * (A @ W) (gather source)
__device__ __half g_a [(size_t)N_NODES * H];     // relu(dis*agg1 + b1) = GEMM-2 input
__device__ float  g_pool[N_GRAPH * H];
__device__ float  g_cnt[N_GRAPH];

// ---------------- setup: histogram, scan(+rsqrt), CSR fill ----------------
__global__ void k_init() {
    int i = blockIdx.x * blockDim.x + threadIdx.x;
    if (i < N_NODES) { g_hist[i] = 0; g_cur[i] = 0; }
    if (i < N_GRAPH * H) g_pool[i] = 0.0f;
    if (i < N_GRAPH) g_cnt[i] = 0.0f;
}

__global__ void k_hist(const int* __restrict__ ei) {
    int i = blockIdx.x * blockDim.x + threadIdx.x;
    if (i < N_EDGES) {
        int d = ei[N_EDGES + i];
        if ((unsigned)d < N_NODES) atomicAdd(&g_hist[d], 1);
    }
}

__global__ __launch_bounds__(SCAN_T) void k_scan_block() {
    __shared__ int sh[SCAN_T];
    int i = blockIdx.x * SCAN_T + threadIdx.x;
    int v = (i < N_NODES) ? g_hist[i] : 0;
    if (i < N_NODES) g_dis[i] = rsqrtf((float)v + 1.0f);   // fused rsqrt (+1 self loop)
    sh[threadIdx.x] = v;
    __syncthreads();
#pragma unroll
    for (int o = 1; o < SCAN_T; o <<= 1) {
        int t = (threadIdx.x >= o) ? sh[threadIdx.x - o] : 0;
        __syncthreads();
        sh[threadIdx.x] += t;
        __syncthreads();
    }
    if (i < N_NODES) g_off[i] = sh[threadIdx.x] - v;               // exclusive
    if (threadIdx.x == SCAN_T - 1) g_bsum[blockIdx.x] = sh[SCAN_T - 1];
}

__global__ void k_scan_top() {
    if (threadIdx.x == 0) {
        int acc = 0;
#pragma unroll 1
        for (int i = 0; i < SCAN_B; i++) { int t = g_bsum[i]; g_bsum[i] = acc; acc += t; }
    }
}

__global__ __launch_bounds__(SCAN_T) void k_scan_add() {
    int i = blockIdx.x * SCAN_T + threadIdx.x;
    if (i < N_NODES) g_off[i] += g_bsum[blockIdx.x];
}

__global__ void k_fill(const int* __restrict__ ei) {
    int i = blockIdx.x * blockDim.x + threadIdx.x;
    if (i < N_EDGES) {
        int s = ei[i];
        int d = ei[N_EDGES + i];
        if ((unsigned)s >= N_NODES || (unsigned)d >= N_NODES) return;
        int pos = g_off[d] + atomicAdd(&g_cur[d], 1);
        g_csrc[pos] = s;
    }
}

// ---------------- tf32 tensor-core GEMM: g_h = dis[row]*(A @ W), fp16 write ------
// CTA tile 64(M) x 128(N) x 128(K fully staged). smem = 103.7KB -> 2 CTAs/SM so
// one CTA's MMA mainloop overlaps the co-resident CTA's global staging.
// 8 warps (4m x 2n), warp tile 16x64 via mma.sync.m16n8k8 (1 m-frag x 8 n-frags).
#define BM 64
#define ASTR 132
#define WSTR 136
#define GEMM_SMEM ((BM * ASTR + 128 * WSTR + 64) * 4)   // 103,680 B

__device__ __forceinline__ float f2tf32(float f) {
    unsigned u;
    asm("cvt.rna.tf32.f32 %0, %1;" : "=r"(u) : "f"(f));
    return __uint_as_float(u);
}

__device__ __forceinline__ void mma_tf32(float& d0, float& d1, float& d2, float& d3,
                                         unsigned a0, unsigned a1, unsigned a2, unsigned a3,
                                         unsigned b0, unsigned b1) {
    asm volatile("mma.sync.aligned.m16n8k8.row.col.f32.tf32.tf32.f32 "
                 "{%0,%1,%2,%3}, {%4,%5,%6,%7}, {%8,%9}, {%0,%1,%2,%3};"
                 : "+f"(d0), "+f"(d1), "+f"(d2), "+f"(d3)
                 : "r"(a0), "r"(a1), "r"(a2), "r"(a3), "r"(b0), "r"(b1));
}

// LAYER==0: A = x (fp32 ext).  LAYER==1: A = g_a (fp16, already relu'd).
template<int LAYER>
__global__ __launch_bounds__(256, 2) void k_gemm(const float* __restrict__ x,
                                                 const float* __restrict__ W) {
    extern __shared__ float smem[];
    float* As   = smem;                          // [BM][ASTR]
    float* Ws   = smem + BM * ASTR;              // [128][WSTR]
    float* sdis = smem + BM * ASTR + 128 * WSTR; // [BM]

    int tid = threadIdx.x;
    int row0 = blockIdx.x * BM;

    if (tid < BM) {
        int gr = row0 + tid;
        sdis[tid] = (gr < N_NODES) ? g_dis[gr] : 0.f;
    }

    // stage W (128x128 fp32 -> tf32): 4096 float4 / 256 thr = 16 each
    const float4* W4 = (const float4*)W;
#pragma unroll
    for (int i = 0; i < 16; i++) {
        int j = tid + i * 256;
        int r = j >> 5, c4 = j & 31;
        float4 v = W4[j];
        *(float4*)&Ws[r * WSTR + c4 * 4] =
            make_float4(f2tf32(v.x), f2tf32(v.y), f2tf32(v.z), f2tf32(v.w));
    }

    if (LAYER == 0) {
        // A tile from x: 64x128 fp32 = 2048 float4 = 8 each
#pragma unroll
        for (int i = 0; i < 8; i++) {
            int j = tid + i * 256;
            int r = j >> 5, c4 = j & 31;
            int gr = row0 + r;
            float4 v = make_float4(0.f, 0.f, 0.f, 0.f);
            if (gr < N_NODES) v = *(const float4*)&x[(size_t)gr * H + c4 * 4];
            *(float4*)&As[r * ASTR + c4 * 4] =
                make_float4(f2tf32(v.x), f2tf32(v.y), f2tf32(v.z), f2tf32(v.w));
        }
    } else {
        // A tile from g_a (fp16): 64 rows x 16 uint4 = 1024 = 4 each
#pragma unroll
        for (int i = 0; i < 4; i++) {
            int j = tid + i * 256;
            int r = j >> 4, c8 = j & 15;
            int gr = row0 + r;
            float o[8];
            if (gr < N_NODES) {
                uint4 u = *(const uint4*)&g_a[(size_t)gr * H + c8 * 8];
                float2 f0 = __half22float2(*(__half2*)&u.x);
                float2 f1 = __half22float2(*(__half2*)&u.y);
                float2 f2 = __half22float2(*(__half2*)&u.z);
                float2 f3 = __half22float2(*(__half2*)&u.w);
                o[0] = f2tf32(f0.x); o[1] = f2tf32(f0.y);
                o[2] = f2tf32(f1.x); o[3] = f2tf32(f1.y);
                o[4] = f2tf32(f2.x); o[5] = f2tf32(f2.y);
                o[6] = f2tf32(f3.x); o[7] = f2tf32(f3.y);
            } else {
#pragma unroll
                for (int t = 0; t < 8; t++) o[t] = 0.f;
            }
            *(float4*)&As[r * ASTR + c8 * 8]     = make_float4(o[0], o[1], o[2], o[3]);
            *(float4*)&As[r * ASTR + c8 * 8 + 4] = make_float4(o[4], o[5], o[6], o[7]);
        }
    }
    __syncthreads();

    int lane = tid & 31, wid = tid >> 5;
    int wm = wid >> 1, wn = wid & 1;            // 4m x 2n warp grid
    int g8 = lane >> 2, tig = lane & 3;

    float acc[8][4];
#pragma unroll
    for (int nf = 0; nf < 8; nf++)
#pragma unroll
        for (int q = 0; q < 4; q++) acc[nf][q] = 0.f;

#pragma unroll 1
    for (int kk = 0; kk < 16; kk++) {
        int k0 = kk * 8;
        int r = wm * 16 + g8;
        unsigned a0 = __float_as_uint(As[r * ASTR + k0 + tig]);
        unsigned a1 = __float_as_uint(As[(r + 8) * ASTR + k0 + tig]);
        unsigned a2 = __float_as_uint(As[r * ASTR + k0 + tig + 4]);
        unsigned a3 = __float_as_uint(As[(r + 8) * ASTR + k0 + tig + 4]);
#pragma unroll
        for (int nf = 0; nf < 8; nf++) {
            int n = wn * 64 + nf * 8 + g8;
            unsigned b0 = __float_as_uint(Ws[(k0 + tig) * WSTR + n]);
            unsigned b1 = __float_as_uint(Ws[(k0 + tig + 4) * WSTR + n]);
            mma_tf32(acc[nf][0], acc[nf][1], acc[nf][2], acc[nf][3],
                     a0, a1, a2, a3, b0, b1);
        }
    }

    // epilogue: scale by dis, fp16 write to g_h
#pragma unroll
    for (int hh = 0; hh < 2; hh++) {
        int lr = wm * 16 + g8 + hh * 8;
        int gr = row0 + lr;
        if (gr >= N_NODES) continue;
        float dsc = sdis[lr];
#pragma unroll
        for (int nf = 0; nf < 8; nf++) {
            float v0 = acc[nf][hh * 2 + 0] * dsc;
            float v1 = acc[nf][hh * 2 + 1] * dsc;
            size_t off = (size_t)gr * H + wn * 64 + nf * 8 + 2 * tig;
            *(__half2*)&g_h[off] = __floats2half2_rn(v0, v1);
        }
    }
}

// ---------------- CSR aggregate: warp/node, prefetched indices, 4-deep pipeline --
// agg = g_h[v] + sum_{src in csr[v]} g_h[src];  r = relu(dis[v]*agg + bias)
// PHASE 0: r -> g_a (fp16, GEMM-2 input).
// PHASE 1: block-staged mean-pool: smem accumulate, 128 global atomics per block.
#define AGG_NPB 8   // nodes per block (8 warps)

__device__ __forceinline__ void acc_row(int s, int lane,
                                        float& a0, float& a1, float& a2, float& a3) {
    uint2 u = *(const uint2*)&g_h[(size_t)s * H + lane * 4];
    float2 p0 = __half22float2(*(__half2*)&u.x);
    float2 p1 = __half22float2(*(__half2*)&u.y);
    a0 += p0.x; a1 += p0.y; a2 += p1.x; a3 += p1.y;
}

template<int PHASE>
__global__ __launch_bounds__(256) void k_agg(const float* __restrict__ bias,
                                             const int* __restrict__ batch) {
    __shared__ float sp[H];
    __shared__ int s_uni;

    int warp = threadIdx.x >> 5;
    int lane = threadIdx.x & 31;
    int v = blockIdx.x * AGG_NPB + warp;

    if (PHASE == 1) {
        if (threadIdx.x < H) sp[threadIdx.x] = 0.f;
        if (threadIdx.x == 0) {
            int v0 = blockIdx.x * AGG_NPB;
            int vl = min(v0 + AGG_NPB - 1, N_NODES - 1);
            int b0 = batch[v0];
            s_uni = (b0 == batch[vl]) ? b0 : -1;
        }
        __syncthreads();
    }

    if (v < N_NODES) {
        // self-loop seed
        float a0, a1, a2, a3;
        {
            uint2 u = *(const uint2*)&g_h[(size_t)v * H + lane * 4];
            float2 f0 = __half22float2(*(__half2*)&u.x);
            float2 f1 = __half22float2(*(__half2*)&u.y);
            a0 = f0.x; a1 = f0.y; a2 = f1.x; a3 = f1.y;
        }

        int beg = g_off[v];
        int deg = g_hist[v];
#pragma unroll 1
        for (int base = 0; base < deg; base += 32) {
            int n = min(32, deg - base);
            // one coalesced load fetches up to 32 neighbor indices
            int myidx = (lane < n) ? __ldg(&g_csrc[beg + base + lane]) : 0;
            int j = 0;
#pragma unroll 1
            for (; j + 4 <= n; j += 4) {         // 4 independent 256B row loads in flight
                int s0 = __shfl_sync(0xffffffffu, myidx, j);
                int s1 = __shfl_sync(0xffffffffu, myidx, j + 1);
                int s2 = __shfl_sync(0xffffffffu, myidx, j + 2);
                int s3 = __shfl_sync(0xffffffffu, myidx, j + 3);
                uint2 u0 = *(const uint2*)&g_h[(size_t)s0 * H + lane * 4];
                uint2 u1 = *(const uint2*)&g_h[(size_t)s1 * H + lane * 4];
                uint2 u2 = *(const uint2*)&g_h[(size_t)s2 * H + lane * 4];
                uint2 u3 = *(const uint2*)&g_h[(size_t)s3 * H + lane * 4];
                float2 p0 = __half22float2(*(__half2*)&u0.x), p1 = __half22float2(*(__half2*)&u0.y);
                float2 q0 = __half22float2(*(__half2*)&u1.x), q1 = __half22float2(*(__half2*)&u1.y);
                float2 r0_ = __half22float2(*(__half2*)&u2.x), r1_ = __half22float2(*(__half2*)&u2.y);
                float2 t0 = __half22float2(*(__half2*)&u3.x), t1 = __half22float2(*(__half2*)&u3.y);
                a0 += (p0.x + q0.x) + (r0_.x + t0.x);
                a1 += (p0.y + q0.y) + (r0_.y + t0.y);
                a2 += (p1.x + q1.x) + (r1_.x + t1.x);
                a3 += (p1.y + q1.y) + (r1_.y + t1.y);
            }
#pragma unroll 1
            for (; j < n; j++) {
                int s0 = __shfl_sync(0xffffffffu, myidx, j);
                acc_row(s0, lane, a0, a1, a2, a3);
            }
        }

        float dsc = g_dis[v];
        float4 bb = *(const float4*)&bias[lane * 4];
        float r0 = fmaxf(fmaf(dsc, a0, bb.x), 0.f);
        float r1 = fmaxf(fmaf(dsc, a1, bb.y), 0.f);
        float r2 = fmaxf(fmaf(dsc, a2, bb.z), 0.f);
        float r3 = fmaxf(fmaf(dsc, a3, bb.w), 0.f);

        if (PHASE == 0) {
            uint2 o;
            *(__half2*)&o.x = __floats2half2_rn(r0, r1);
            *(__half2*)&o.y = __floats2half2_rn(r2, r3);
            *(uint2*)&g_a[(size_t)v * H + lane * 4] = o;
        } else {
            if (s_uni >= 0) {                    // whole block same graph: stage in smem
                atomicAdd(&sp[lane * 4 + 0], r0);
                atomicAdd(&sp[lane * 4 + 1], r1);
                atomicAdd(&sp[lane * 4 + 2], r2);
                atomicAdd(&sp[lane * 4 + 3], r3);
            } else {                             // graph boundary block (rare): direct
                int b = __ldg(&batch[v]);
                float* pp = &g_pool[b * H + lane * 4];
                atomicAdd(pp + 0, r0);
                atomicAdd(pp + 1, r1);
                atomicAdd(pp + 2, r2);
                atomicAdd(pp + 3, r3);
                if (lane == 0) atomicAdd(&g_cnt[b], 1.0f);
            }
        }
    }

    if (PHASE == 1) {
        __syncthreads();
        if (s_uni >= 0) {
            if (threadIdx.x < H) atomicAdd(&g_pool[s_uni * H + threadIdx.x], sp[threadIdx.x]);
            if (threadIdx.x == 0) {
                int cnt = min(AGG_NPB, N_NODES - blockIdx.x * AGG_NPB);
                atomicAdd(&g_cnt[s_uni], (float)cnt);
            }
        }
    }
}

// ---------------- head MLP: 64 blocks, one per graph ----------------
__global__ __launch_bounds__(256) void k_mlp(const float* __restrict__ sv,
                                             const float* __restrict__ act,
                                             const float* __restrict__ Wf1, const float* __restrict__ bf1,
                                             const float* __restrict__ Wf2, const float* __restrict__ bf2,
                                             const float* __restrict__ Wo,  const float* __restrict__ bo,
                                             float* __restrict__ out) {
    int g = blockIdx.x;
    int t = threadIdx.x;
    __shared__ float z[ZDIM];
    __shared__ float z1[256];
    __shared__ float z2[256];
    __shared__ float red[8];

    if (t < ZDIM) {
        float v;
        if (t < 128)      v = g_pool[g * H + t] / fmaxf(g_cnt[g], 1.0f);
        else if (t < 192) v = sv[g * 64 + (t - 128)];
        else              v = act[g * 32 + (t - 192)];
        z[t] = v;
    }
    __syncthreads();

    float a = bf1[t];
#pragma unroll 8
    for (int k = 0; k < ZDIM; k++) a = fmaf(z[k], Wf1[k * 256 + t], a);
    z1[t] = fmaxf(a, 0.f);
    __syncthreads();

    a = bf2[t];
#pragma unroll 8
    for (int k = 0; k < 256; k++) a = fmaf(z1[k], Wf2[k * 256 + t], a);
    z2[t] = fmaxf(a, 0.f);
    __syncthreads();

    float p = z2[t] * Wo[t];
#pragma unroll
    for (int o = 16; o > 0; o >>= 1) p += __shfl_down_sync(0xffffffffu, p, o);
    if ((t & 31) == 0) red[t >> 5] = p;
    __syncthreads();
    if (t == 0) {
        float sacc = 0.f;
#pragma unroll
        for (int i = 0; i < 8; i++) sacc += red[i];
        out[g] = sacc + bo[0];
    }
}

// ---------------- launch ----------------
extern "C" void kernel_launch(void* const* d_in, const int* in_sizes, int n_in,
                              void* d_out, int out_size) {
    const float* x     = (const float*)d_in[0];
    const int*   ei    = (const int*)d_in[1];
    const int*   batch = (const int*)d_in[2];
    const float* sv    = (const float*)d_in[3];
    const float* act   = (const float*)d_in[4];
    const float* W1    = (const float*)d_in[5];
    const float* b1    = (const float*)d_in[6];
    const float* W2    = (const float*)d_in[7];
    const float* b2    = (const float*)d_in[8];
    const float* Wf1   = (const float*)d_in[9];
    const float* bf1   = (const float*)d_in[10];
    const float* Wf2   = (const float*)d_in[11];
    const float* bf2   = (const float*)d_in[12];
    const float* Wo    = (const float*)d_in[13];
    const float* bo    = (const float*)d_in[14];
    float* out = (float*)d_out;

    cudaFuncSetAttribute(k_gemm<0>, cudaFuncAttributeMaxDynamicSharedMemorySize, GEMM_SMEM);
    cudaFuncSetAttribute(k_gemm<1>, cudaFuncAttributeMaxDynamicSharedMemorySize, GEMM_SMEM);

    // setup + CSR build (reused by both layers)
    k_init      <<<(N_NODES + 255) / 256, 256>>>();
    k_hist      <<<(N_EDGES + 255) / 256, 256>>>(ei);
    k_scan_block<<<SCAN_B, SCAN_T>>>();              // also emits g_dis
    k_scan_top  <<<1, 32>>>();
    k_scan_add  <<<SCAN_B, SCAN_T>>>();
    k_fill      <<<(N_EDGES + 255) / 256, 256>>>(ei);

    int gemm_blocks = (N_NODES + BM - 1) / BM;              // 1563
    int agg_blocks  = (N_NODES + AGG_NPB - 1) / AGG_NPB;    // 12500

    k_gemm<0><<<gemm_blocks, 256, GEMM_SMEM>>>(x, W1);
    k_agg<0> <<<agg_blocks, 256>>>(b1, batch);              // -> g_a
    k_gemm<1><<<gemm_blocks, 256, GEMM_SMEM>>>(x, W2);
    k_agg<1> <<<agg_blocks, 256>>>(b2, batch);              // -> g_pool (block-staged)

    k_mlp<<<N_GRAPH, 256>>>(sv, act, Wf1, bf1, Wf2, bf2, Wo, bo, out);
}